// round 1
// baseline (speedup 1.0000x reference)
#include <cuda_runtime.h>
#include <math.h>

// ---------------- problem constants ----------------
#define BATCH 2
#define HW 256            // H = W = 256
#define CH 192
#define HEADS 6
#define HD 32             // head dim
#define WS 8
#define NTOK 64           // tokens per window
#define NWIN_SIDE 32      // 256/8
#define NWIN_IMG 1024     // 32*32
#define MTOT (BATCH * HW * HW)       // 131072 rows
#define HIDDEN 768

// ---------------- scratch (static device globals; no allocs allowed) ----------------
__device__ float g_xn  [(size_t)MTOT * CH];       // LN1 output
__device__ float g_qkv [(size_t)MTOT * 3 * CH];   // qkv in window order
__device__ float g_attn[(size_t)MTOT * CH];       // attention output (window order)
__device__ float g_x1  [(size_t)MTOT * CH];       // residual 1
__device__ float g_h2  [(size_t)MTOT * CH];       // LN2 output
__device__ float g_hid [(size_t)MTOT * HIDDEN];   // MLP hidden

// window-token index m -> spatial row index (shift fold). Scatter target == gather source.
__device__ __forceinline__ int gather_row(int m) {
    int win = m >> 6, n = m & 63;
    int b   = win >> 10, rem = win & 1023;
    int wh  = rem >> 5,  ww  = rem & 31;
    int r   = n >> 3,    c   = n & 7;
    int hs  = (wh * 8 + r + 4) & 255;
    int ws_ = (ww * 8 + c + 4) & 255;
    return (b << 16) | (hs << 8) | ws_;
}

// ---------------- LayerNorm: one warp per row of 192 ----------------
__global__ void ln_kernel(const float* __restrict__ in, const float* __restrict__ g,
                          const float* __restrict__ b, float* __restrict__ out, int M) {
    int row  = blockIdx.x * (blockDim.x >> 5) + (threadIdx.x >> 5);
    int lane = threadIdx.x & 31;
    if (row >= M) return;
    const float* rp = in + (size_t)row * CH;
    float v[6];
    float s = 0.f;
#pragma unroll
    for (int i = 0; i < 6; i++) { v[i] = rp[lane + 32 * i]; s += v[i]; }
#pragma unroll
    for (int o = 16; o; o >>= 1) s += __shfl_xor_sync(0xffffffffu, s, o);
    float mean = s * (1.f / 192.f);
    float q = 0.f;
#pragma unroll
    for (int i = 0; i < 6; i++) { float d = v[i] - mean; q += d * d; }
#pragma unroll
    for (int o = 16; o; o >>= 1) q += __shfl_xor_sync(0xffffffffu, q, o);
    float inv = rsqrtf(q * (1.f / 192.f) + 1e-5f);
    float* op = out + (size_t)row * CH;
#pragma unroll
    for (int i = 0; i < 6; i++) {
        int col = lane + 32 * i;
        op[col] = (v[i] - mean) * inv * g[col] + b[col];
    }
}

// ---------------- generic 128x128x8 SGEMM: C[m,n] = sum_k A[m,k] * W[n,k] ----------------
// EPI: 0 = store; 1 = +bias, exact GELU; 2 = scatter row via gather_row, += res[gathered]; 3 = += res[m]
template<int EPI, bool GATHER>
__global__ void __launch_bounds__(256) gemm128(
    const float* __restrict__ A, const float* __restrict__ W,
    const float* __restrict__ bias, const float* __restrict__ res,
    float* __restrict__ C, int K, int N)
{
    __shared__ float As[8][128];
    __shared__ float Bs[8][128];
    const int m0 = blockIdx.x * 128;
    const int n0 = blockIdx.y * 128;
    const int t  = threadIdx.x;

    const int arow = t >> 1;
    const int acol = (t & 1) * 4;
    const int agrow = GATHER ? gather_row(m0 + arow) : (m0 + arow);
    const float* Ap = A + (size_t)agrow * K + acol;

    const int brow = t >> 1;
    const int bcol = (t & 1) * 4;
    const bool bv = (n0 + brow) < N;
    const float* Wp = W + (size_t)(bv ? (n0 + brow) : 0) * K + bcol;

    const int ty = t >> 4, tx = t & 15;
    float acc[8][8];
#pragma unroll
    for (int i = 0; i < 8; i++)
#pragma unroll
        for (int j = 0; j < 8; j++) acc[i][j] = 0.f;

    for (int k0 = 0; k0 < K; k0 += 8) {
        float4 a4 = *(const float4*)(Ap + k0);
        float4 b4 = bv ? *(const float4*)(Wp + k0) : make_float4(0.f, 0.f, 0.f, 0.f);
        __syncthreads();
        As[acol + 0][arow] = a4.x; As[acol + 1][arow] = a4.y;
        As[acol + 2][arow] = a4.z; As[acol + 3][arow] = a4.w;
        Bs[bcol + 0][brow] = b4.x; Bs[bcol + 1][brow] = b4.y;
        Bs[bcol + 2][brow] = b4.z; Bs[bcol + 3][brow] = b4.w;
        __syncthreads();
#pragma unroll
        for (int kk = 0; kk < 8; kk++) {
            float ar[8], br[8];
            *(float4*)&ar[0] = *(const float4*)&As[kk][ty * 8];
            *(float4*)&ar[4] = *(const float4*)&As[kk][ty * 8 + 4];
            *(float4*)&br[0] = *(const float4*)&Bs[kk][tx * 8];
            *(float4*)&br[4] = *(const float4*)&Bs[kk][tx * 8 + 4];
#pragma unroll
            for (int i = 0; i < 8; i++)
#pragma unroll
                for (int j = 0; j < 8; j++)
                    acc[i][j] = fmaf(ar[i], br[j], acc[i][j]);
        }
    }

#pragma unroll
    for (int i = 0; i < 8; i++) {
        int m = m0 + ty * 8 + i;
        int orow = (EPI == 2) ? gather_row(m) : m;
#pragma unroll
        for (int j = 0; j < 8; j++) {
            int nn = n0 + tx * 8 + j;
            if (nn < N) {
                float v = acc[i][j];
                if (bias) v += __ldg(&bias[nn]);
                if (EPI == 1) v = 0.5f * v * (1.f + erff(v * 0.70710678118654752f));
                if (EPI >= 2) v += res[(size_t)orow * N + nn];
                C[(size_t)orow * N + nn] = v;
            }
        }
    }
}

// ---------------- windowed attention: one block per (window, head), 64 threads ----------------
__device__ __forceinline__ int region(int p) { return p < 248 ? 0 : (p < 252 ? 1 : 2); }

__global__ void __launch_bounds__(64) attn_kernel(const float* __restrict__ qkv,
                                                  const float* __restrict__ rpb,
                                                  float* __restrict__ out) {
    __shared__ float sk[64][32];
    __shared__ float sv[64][32];
    __shared__ float sp[64][65];
    __shared__ float srpb[225];

    const int win = blockIdx.x;
    const int h   = blockIdx.y;
    const int n   = threadIdx.x;

    for (int i = n; i < 225; i += 64) srpb[i] = rpb[i * HEADS + h];

    const size_t base = (size_t)(win * 64 + n) * (3 * CH) + h * HD;
    const float scale = 0.17677669529663687f;  // 1/sqrt(32)

    float q[32];
    {
        const float4* qp = (const float4*)(qkv + base);
        const float4* kp = (const float4*)(qkv + base + CH);
        const float4* vp = (const float4*)(qkv + base + 2 * CH);
#pragma unroll
        for (int i = 0; i < 8; i++) {
            float4 t4 = qp[i];
            q[i * 4 + 0] = t4.x * scale; q[i * 4 + 1] = t4.y * scale;
            q[i * 4 + 2] = t4.z * scale; q[i * 4 + 3] = t4.w * scale;
            ((float4*)sk[n])[i] = kp[i];
            ((float4*)sv[n])[i] = vp[i];
        }
    }
    __syncthreads();

    const int rem = win & 1023;
    const int wh = rem >> 5, ww = rem & 31;
    const int ri = n >> 3, ci = n & 7;
    const int idi = region(wh * 8 + ri) * 3 + region(ww * 8 + ci);

    float mx = -1e30f;
    for (int j = 0; j < 64; j++) {
        float a = 0.f;
#pragma unroll
        for (int d4 = 0; d4 < 8; d4++) {
            float4 kv = *(const float4*)&sk[j][d4 * 4];
            a = fmaf(q[d4 * 4 + 0], kv.x, a);
            a = fmaf(q[d4 * 4 + 1], kv.y, a);
            a = fmaf(q[d4 * 4 + 2], kv.z, a);
            a = fmaf(q[d4 * 4 + 3], kv.w, a);
        }
        int rj = j >> 3, cj = j & 7;
        a += srpb[(ri - rj + 7) * 15 + (ci - cj + 7)];
        int idj = region(wh * 8 + rj) * 3 + region(ww * 8 + cj);
        if (idi != idj) a -= 100.f;
        sp[n][j] = a;
        mx = fmaxf(mx, a);
    }

    float sum = 0.f;
    for (int j = 0; j < 64; j++) {
        float e = __expf(sp[n][j] - mx);
        sp[n][j] = e;
        sum += e;
    }
    float inv = 1.f / sum;

    float o[32];
#pragma unroll
    for (int d = 0; d < 32; d++) o[d] = 0.f;
    for (int j = 0; j < 64; j++) {
        float p = sp[n][j];
#pragma unroll
        for (int d4 = 0; d4 < 8; d4++) {
            float4 vv = *(const float4*)&sv[j][d4 * 4];
            o[d4 * 4 + 0] = fmaf(p, vv.x, o[d4 * 4 + 0]);
            o[d4 * 4 + 1] = fmaf(p, vv.y, o[d4 * 4 + 1]);
            o[d4 * 4 + 2] = fmaf(p, vv.z, o[d4 * 4 + 2]);
            o[d4 * 4 + 3] = fmaf(p, vv.w, o[d4 * 4 + 3]);
        }
    }

    float* op = out + (size_t)(win * 64 + n) * CH + h * HD;
#pragma unroll
    for (int d4 = 0; d4 < 8; d4++) {
        float4 ov;
        ov.x = o[d4 * 4 + 0] * inv; ov.y = o[d4 * 4 + 1] * inv;
        ov.z = o[d4 * 4 + 2] * inv; ov.w = o[d4 * 4 + 3] * inv;
        *(float4*)&op[d4 * 4] = ov;
    }
}

// ---------------- launcher ----------------
extern "C" void kernel_launch(void* const* d_in, const int* in_sizes, int n_in,
                              void* d_out, int out_size) {
    const float* x       = (const float*)d_in[0];
    const float* norm1_g = (const float*)d_in[1];
    const float* norm1_b = (const float*)d_in[2];
    const float* qkv_w   = (const float*)d_in[3];
    const float* rpb     = (const float*)d_in[4];
    const float* proj_w  = (const float*)d_in[5];
    const float* proj_b  = (const float*)d_in[6];
    const float* norm2_g = (const float*)d_in[7];
    const float* norm2_b = (const float*)d_in[8];
    const float* mlp_w1  = (const float*)d_in[9];
    const float* mlp_b1  = (const float*)d_in[10];
    const float* mlp_w2  = (const float*)d_in[11];
    const float* mlp_b2  = (const float*)d_in[12];
    float* out = (float*)d_out;

    float *xn, *qkvb, *attnb, *x1, *h2, *hid;
    cudaGetSymbolAddress((void**)&xn,    g_xn);
    cudaGetSymbolAddress((void**)&qkvb,  g_qkv);
    cudaGetSymbolAddress((void**)&attnb, g_attn);
    cudaGetSymbolAddress((void**)&x1,    g_x1);
    cudaGetSymbolAddress((void**)&h2,    g_h2);
    cudaGetSymbolAddress((void**)&hid,   g_hid);

    const int M = MTOT;                 // 131072
    const int LN_BLOCKS = M / 8;        // 8 rows (warps) per 256-thread block

    // 1. LN1
    ln_kernel<<<LN_BLOCKS, 256>>>(x, norm1_g, norm1_b, xn, M);

    // 2. QKV GEMM (gathered rows = shift + window partition), N = 576
    gemm128<0, true><<<dim3(M / 128, 5), 256>>>(xn, qkv_w, nullptr, nullptr, qkvb, CH, 3 * CH);

    // 3. windowed attention
    attn_kernel<<<dim3(BATCH * NWIN_IMG, HEADS), 64>>>(qkvb, rpb, attnb);

    // 4. proj GEMM + scatter (window reverse + roll back) + residual -> x1
    gemm128<2, false><<<dim3(M / 128, 2), 256>>>(attnb, proj_w, proj_b, x, x1, CH, CH);

    // 5. LN2
    ln_kernel<<<LN_BLOCKS, 256>>>(x1, norm2_g, norm2_b, h2, M);

    // 6. MLP1 (bias + exact GELU), N = 768
    gemm128<1, false><<<dim3(M / 128, 6), 256>>>(h2, mlp_w1, mlp_b1, nullptr, hid, CH, HIDDEN);

    // 7. MLP2 (bias + residual) -> output
    gemm128<3, false><<<dim3(M / 128, 2), 256>>>(hid, mlp_w2, mlp_b2, x1, out, HIDDEN, CH);
}

// round 2
// speedup vs baseline: 1.9995x; 1.9995x over previous
#include <cuda_runtime.h>
#include <cuda_bf16.h>
#include <math.h>

// ---------------- problem constants ----------------
#define BATCH 2
#define CH 192
#define HEADS 6
#define HD 32
#define MTOT 131072
#define HIDDEN 768

// ---------------- scratch ----------------
__device__ __nv_bfloat16 gb_xn  [(size_t)MTOT * CH];
__device__ __nv_bfloat16 gb_qkv [(size_t)MTOT * 3 * CH];
__device__ __nv_bfloat16 gb_attn[(size_t)MTOT * CH];
__device__ float         g_x1   [(size_t)MTOT * CH];
__device__ __nv_bfloat16 gb_h2  [(size_t)MTOT * CH];
__device__ __nv_bfloat16 gb_hid [(size_t)MTOT * HIDDEN];
// converted weights, packed: qkv(110592) | proj(36864) | w1(147456) | w2(147456)
__device__ __nv_bfloat16 gb_w[576*192 + 192*192 + 768*192 + 192*768];

__device__ __forceinline__ int gather_row(int m) {
    int win = m >> 6, n = m & 63;
    int b   = win >> 10, rem = win & 1023;
    int wh  = rem >> 5,  ww  = rem & 31;
    int r   = n >> 3,    c   = n & 7;
    int hs  = (wh * 8 + r + 4) & 255;
    int ws_ = (ww * 8 + c + 4) & 255;
    return (b << 16) | (hs << 8) | ws_;
}

__device__ __forceinline__ unsigned smem_u32(const void* p) {
    return (unsigned)__cvta_generic_to_shared(p);
}

// ---------------- fp32 -> bf16 convert ----------------
__global__ void f2bf_kernel(const float* __restrict__ in, __nv_bfloat16* __restrict__ out, int n) {
    int i = blockIdx.x * 256 + threadIdx.x;
    if (i < n) out[i] = __float2bfloat16(in[i]);
}

// ---------------- LayerNorm: one warp per row of 192, bf16 out ----------------
__global__ void ln_kernel(const float* __restrict__ in, const float* __restrict__ g,
                          const float* __restrict__ b, __nv_bfloat16* __restrict__ out, int M) {
    int row  = blockIdx.x * (blockDim.x >> 5) + (threadIdx.x >> 5);
    int lane = threadIdx.x & 31;
    if (row >= M) return;
    const float* rp = in + (size_t)row * CH;
    float v[6];
    float s = 0.f;
#pragma unroll
    for (int i = 0; i < 6; i++) { v[i] = rp[lane + 32 * i]; s += v[i]; }
#pragma unroll
    for (int o = 16; o; o >>= 1) s += __shfl_xor_sync(0xffffffffu, s, o);
    float mean = s * (1.f / 192.f);
    float q = 0.f;
#pragma unroll
    for (int i = 0; i < 6; i++) { float d = v[i] - mean; q += d * d; }
#pragma unroll
    for (int o = 16; o; o >>= 1) q += __shfl_xor_sync(0xffffffffu, q, o);
    float inv = rsqrtf(q * (1.f / 192.f) + 1e-5f);
    __nv_bfloat16* op = out + (size_t)row * CH;
#pragma unroll
    for (int i = 0; i < 6; i++) {
        int col = lane + 32 * i;
        op[col] = __float2bfloat16((v[i] - mean) * inv * g[col] + b[col]);
    }
}

// ---------------- HMMA bf16 GEMM, 128x128 tile, 8 warps of 64x32 ----------------
// C[m,n] = sum_k A[m,k] * W[n,k]
// EPI: 0 = store bf16; 1 = +bias, exact GELU, bf16; 2 = scatter row, +res[gathered], fp32; 3 = +bias, +res[m], fp32
template<int EPI, bool GATHER>
__global__ void __launch_bounds__(256) gemm_mma(
    const __nv_bfloat16* __restrict__ A, const __nv_bfloat16* __restrict__ W,
    const float* __restrict__ bias, const float* __restrict__ res,
    void* __restrict__ Cout, int K, int N)
{
    __shared__ __nv_bfloat16 As[2][128][24];
    __shared__ __nv_bfloat16 Bs[2][128][24];
    const int m0 = blockIdx.x * 128, n0 = blockIdx.y * 128;
    const int t = threadIdx.x, lane = t & 31, wid = t >> 5;
    const int wm = wid & 1, wn = wid >> 1;   // 2 (M) x 4 (N) warps

    // gmem->smem load coords: 16B per thread
    const int lrow = t >> 1, lc8 = (t & 1) * 8;
    const int agrow = GATHER ? gather_row(m0 + lrow) : (m0 + lrow);
    const __nv_bfloat16* Ap = A + (size_t)agrow * K + lc8;
    int brow_g = n0 + lrow; if (brow_g >= N) brow_g = 0;   // clamp (cols >= N never stored)
    const __nv_bfloat16* Wp = W + (size_t)brow_g * K + lc8;

    float acc[4][4][4];
#pragma unroll
    for (int i = 0; i < 4; i++)
#pragma unroll
        for (int j = 0; j < 4; j++)
#pragma unroll
            for (int q = 0; q < 4; q++) acc[i][j][q] = 0.f;

    const int nk = K >> 4;
    // prefetch stage 0
    {
        unsigned da = smem_u32(&As[0][lrow][lc8]);
        unsigned db = smem_u32(&Bs[0][lrow][lc8]);
        asm volatile("cp.async.cg.shared.global [%0], [%1], 16;\n" :: "r"(da), "l"(Ap));
        asm volatile("cp.async.cg.shared.global [%0], [%1], 16;\n" :: "r"(db), "l"(Wp));
        asm volatile("cp.async.commit_group;\n");
    }

    const int r16 = lane & 15, ch = lane >> 4;   // ldmatrix addressing

    for (int ks = 0; ks < nk; ks++) {
        if (ks + 1 < nk) {
            int buf = (ks + 1) & 1;
            unsigned da = smem_u32(&As[buf][lrow][lc8]);
            unsigned db = smem_u32(&Bs[buf][lrow][lc8]);
            const __nv_bfloat16* ap = Ap + (ks + 1) * 16;
            const __nv_bfloat16* wp = Wp + (ks + 1) * 16;
            asm volatile("cp.async.cg.shared.global [%0], [%1], 16;\n" :: "r"(da), "l"(ap));
            asm volatile("cp.async.cg.shared.global [%0], [%1], 16;\n" :: "r"(db), "l"(wp));
            asm volatile("cp.async.commit_group;\n");
            asm volatile("cp.async.wait_group 1;\n");
        } else {
            asm volatile("cp.async.wait_group 0;\n");
        }
        __syncthreads();

        const int buf = ks & 1;
        unsigned a[4][4], b[2][4];
#pragma unroll
        for (int i = 0; i < 4; i++) {
            unsigned addr = smem_u32(&As[buf][wm * 64 + i * 16 + r16][ch * 8]);
            asm volatile("ldmatrix.sync.aligned.m8n8.x4.shared.b16 {%0,%1,%2,%3}, [%4];"
                : "=r"(a[i][0]), "=r"(a[i][1]), "=r"(a[i][2]), "=r"(a[i][3]) : "r"(addr));
        }
#pragma unroll
        for (int j2 = 0; j2 < 2; j2++) {
            unsigned addr = smem_u32(&Bs[buf][wn * 32 + j2 * 16 + r16][ch * 8]);
            asm volatile("ldmatrix.sync.aligned.m8n8.x4.shared.b16 {%0,%1,%2,%3}, [%4];"
                : "=r"(b[j2][0]), "=r"(b[j2][1]), "=r"(b[j2][2]), "=r"(b[j2][3]) : "r"(addr));
        }
#pragma unroll
        for (int i = 0; i < 4; i++)
#pragma unroll
            for (int j = 0; j < 4; j++) {
                unsigned b0 = b[j >> 1][j & 1], b1 = b[j >> 1][(j & 1) + 2];
                asm volatile(
                    "mma.sync.aligned.m16n8k16.row.col.f32.bf16.bf16.f32 "
                    "{%0,%1,%2,%3}, {%4,%5,%6,%7}, {%8,%9}, {%0,%1,%2,%3};"
                    : "+f"(acc[i][j][0]), "+f"(acc[i][j][1]), "+f"(acc[i][j][2]), "+f"(acc[i][j][3])
                    : "r"(a[i][0]), "r"(a[i][1]), "r"(a[i][2]), "r"(a[i][3]), "r"(b0), "r"(b1));
            }
        __syncthreads();
    }

    // epilogue
#pragma unroll
    for (int i = 0; i < 4; i++) {
        int rbase = m0 + wm * 64 + i * 16 + (lane >> 2);
#pragma unroll
        for (int j = 0; j < 4; j++) {
            int c = n0 + wn * 32 + j * 8 + (lane & 3) * 2;
            if (c < N) {
#pragma unroll
                for (int h = 0; h < 2; h++) {
                    int r = rbase + h * 8;
                    float v0 = acc[i][j][h * 2 + 0];
                    float v1 = acc[i][j][h * 2 + 1];
                    if (bias) { v0 += __ldg(&bias[c]); v1 += __ldg(&bias[c + 1]); }
                    if (EPI == 1) {
                        v0 = 0.5f * v0 * (1.f + erff(v0 * 0.70710678118654752f));
                        v1 = 0.5f * v1 * (1.f + erff(v1 * 0.70710678118654752f));
                    }
                    if (EPI >= 2) {
                        int orow = (EPI == 2) ? gather_row(r) : r;
                        size_t off = (size_t)orow * N + c;
                        float2 rv = *(const float2*)(res + off);
                        float2 ov; ov.x = v0 + rv.x; ov.y = v1 + rv.y;
                        *(float2*)((float*)Cout + off) = ov;
                    } else {
                        __nv_bfloat162 p;
                        p.x = __float2bfloat16(v0); p.y = __float2bfloat16(v1);
                        *(__nv_bfloat162*)((__nv_bfloat16*)Cout + (size_t)r * N + c) = p;
                    }
                }
            }
        }
    }
}

// ---------------- windowed attention: one block per (window, head), 64 threads ----------------
__device__ __forceinline__ int region(int p) { return p < 248 ? 0 : (p < 252 ? 1 : 2); }

__global__ void __launch_bounds__(64) attn_kernel(const __nv_bfloat16* __restrict__ qkv,
                                                  const float* __restrict__ rpb,
                                                  __nv_bfloat16* __restrict__ out) {
    __shared__ float sk[64][32];
    __shared__ float sv[64][32];
    __shared__ float sp[64][65];
    __shared__ float srpb[225];

    const int win = blockIdx.x;
    const int h   = blockIdx.y;
    const int n   = threadIdx.x;

    for (int i = n; i < 225; i += 64) srpb[i] = rpb[i * HEADS + h];

    const size_t base = (size_t)(win * 64 + n) * (3 * CH) + h * HD;
    const float scale = 0.17677669529663687f;  // 1/sqrt(32)

    float q[32];
    {
        const __nv_bfloat162* qp = (const __nv_bfloat162*)(qkv + base);
        const __nv_bfloat162* kp = (const __nv_bfloat162*)(qkv + base + CH);
        const __nv_bfloat162* vp = (const __nv_bfloat162*)(qkv + base + 2 * CH);
#pragma unroll
        for (int i = 0; i < 16; i++) {
            float2 fq = __bfloat1622float2(qp[i]);
            float2 fk = __bfloat1622float2(kp[i]);
            float2 fv = __bfloat1622float2(vp[i]);
            q[2 * i] = fq.x * scale; q[2 * i + 1] = fq.y * scale;
            sk[n][2 * i] = fk.x; sk[n][2 * i + 1] = fk.y;
            sv[n][2 * i] = fv.x; sv[n][2 * i + 1] = fv.y;
        }
    }
    __syncthreads();

    const int rem = win & 1023;
    const int wh = rem >> 5, ww = rem & 31;
    const int ri = n >> 3, ci = n & 7;
    const int idi = region(wh * 8 + ri) * 3 + region(ww * 8 + ci);

    float mx = -1e30f;
    for (int j = 0; j < 64; j++) {
        float a = 0.f;
#pragma unroll
        for (int d4 = 0; d4 < 8; d4++) {
            float4 kv = *(const float4*)&sk[j][d4 * 4];
            a = fmaf(q[d4 * 4 + 0], kv.x, a);
            a = fmaf(q[d4 * 4 + 1], kv.y, a);
            a = fmaf(q[d4 * 4 + 2], kv.z, a);
            a = fmaf(q[d4 * 4 + 3], kv.w, a);
        }
        int rj = j >> 3, cj = j & 7;
        a += srpb[(ri - rj + 7) * 15 + (ci - cj + 7)];
        int idj = region(wh * 8 + rj) * 3 + region(ww * 8 + cj);
        if (idi != idj) a -= 100.f;
        sp[n][j] = a;
        mx = fmaxf(mx, a);
    }

    float sum = 0.f;
    for (int j = 0; j < 64; j++) {
        float e = __expf(sp[n][j] - mx);
        sp[n][j] = e;
        sum += e;
    }
    float inv = 1.f / sum;

    float o[32];
#pragma unroll
    for (int d = 0; d < 32; d++) o[d] = 0.f;
    for (int j = 0; j < 64; j++) {
        float p = sp[n][j];
#pragma unroll
        for (int d4 = 0; d4 < 8; d4++) {
            float4 vv = *(const float4*)&sv[j][d4 * 4];
            o[d4 * 4 + 0] = fmaf(p, vv.x, o[d4 * 4 + 0]);
            o[d4 * 4 + 1] = fmaf(p, vv.y, o[d4 * 4 + 1]);
            o[d4 * 4 + 2] = fmaf(p, vv.z, o[d4 * 4 + 2]);
            o[d4 * 4 + 3] = fmaf(p, vv.w, o[d4 * 4 + 3]);
        }
    }

    __nv_bfloat16* op = out + (size_t)(win * 64 + n) * CH + h * HD;
#pragma unroll
    for (int d2 = 0; d2 < 16; d2++) {
        __nv_bfloat162 p;
        p.x = __float2bfloat16(o[2 * d2] * inv);
        p.y = __float2bfloat16(o[2 * d2 + 1] * inv);
        *(__nv_bfloat162*)&op[2 * d2] = p;
    }
}

// ---------------- launcher ----------------
extern "C" void kernel_launch(void* const* d_in, const int* in_sizes, int n_in,
                              void* d_out, int out_size) {
    const float* x       = (const float*)d_in[0];
    const float* norm1_g = (const float*)d_in[1];
    const float* norm1_b = (const float*)d_in[2];
    const float* qkv_w   = (const float*)d_in[3];
    const float* rpb     = (const float*)d_in[4];
    const float* proj_w  = (const float*)d_in[5];
    const float* proj_b  = (const float*)d_in[6];
    const float* norm2_g = (const float*)d_in[7];
    const float* norm2_b = (const float*)d_in[8];
    const float* mlp_w1  = (const float*)d_in[9];
    const float* mlp_b1  = (const float*)d_in[10];
    const float* mlp_w2  = (const float*)d_in[11];
    const float* mlp_b2  = (const float*)d_in[12];
    float* out = (float*)d_out;

    __nv_bfloat16 *xn, *qkvb, *attnb, *h2, *hid, *wbuf;
    float* x1;
    cudaGetSymbolAddress((void**)&xn,    gb_xn);
    cudaGetSymbolAddress((void**)&qkvb,  gb_qkv);
    cudaGetSymbolAddress((void**)&attnb, gb_attn);
    cudaGetSymbolAddress((void**)&x1,    g_x1);
    cudaGetSymbolAddress((void**)&h2,    gb_h2);
    cudaGetSymbolAddress((void**)&hid,   gb_hid);
    cudaGetSymbolAddress((void**)&wbuf,  gb_w);

    __nv_bfloat16* wq  = wbuf;
    __nv_bfloat16* wp  = wbuf + 576 * 192;
    __nv_bfloat16* w1  = wp   + 192 * 192;
    __nv_bfloat16* w2  = w1   + 768 * 192;

    const int M = MTOT;
    const int LN_BLOCKS = M / 8;

    // 0. convert weights to bf16
    f2bf_kernel<<<(576 * 192 + 255) / 256, 256>>>(qkv_w,  wq, 576 * 192);
    f2bf_kernel<<<(192 * 192 + 255) / 256, 256>>>(proj_w, wp, 192 * 192);
    f2bf_kernel<<<(768 * 192 + 255) / 256, 256>>>(mlp_w1, w1, 768 * 192);
    f2bf_kernel<<<(192 * 768 + 255) / 256, 256>>>(mlp_w2, w2, 192 * 768);

    // 1. LN1 -> bf16
    ln_kernel<<<LN_BLOCKS, 256>>>(x, norm1_g, norm1_b, xn, M);

    // 2. QKV GEMM (gathered rows = shift + window partition), N = 576
    gemm_mma<0, true><<<dim3(M / 128, 5), 256>>>(xn, wq, nullptr, nullptr, qkvb, CH, 3 * CH);

    // 3. windowed attention
    attn_kernel<<<dim3(2048, HEADS), 64>>>(qkvb, rpb, attnb);

    // 4. proj GEMM + scatter + residual -> x1 (fp32)
    gemm_mma<2, false><<<dim3(M / 128, 2), 256>>>(attnb, wp, proj_b, x, x1, CH, CH);

    // 5. LN2 -> bf16
    ln_kernel<<<LN_BLOCKS, 256>>>(x1, norm2_g, norm2_b, h2, M);

    // 6. MLP1 (bias + exact GELU) -> bf16, N = 768
    gemm_mma<1, false><<<dim3(M / 128, 6), 256>>>(h2, w1, mlp_b1, nullptr, hid, CH, HIDDEN);

    // 7. MLP2 (bias + residual) -> fp32 output
    gemm_mma<3, false><<<dim3(M / 128, 2), 256>>>(hid, w2, mlp_b2, x1, out, HIDDEN, CH);
}

// round 3
// speedup vs baseline: 2.5185x; 1.2596x over previous
#include <cuda_runtime.h>
#include <cuda_bf16.h>
#include <math.h>

// ---------------- problem constants ----------------
#define BATCH 2
#define CH 192
#define HEADS 6
#define HD 32
#define MTOT 131072
#define HIDDEN 768

// ---------------- scratch ----------------
__device__ __nv_bfloat16 gb_xn  [(size_t)MTOT * CH];
__device__ __nv_bfloat16 gb_qkv [(size_t)MTOT * 3 * CH];
__device__ __nv_bfloat16 gb_attn[(size_t)MTOT * CH];
__device__ float         g_x1   [(size_t)MTOT * CH];
__device__ __nv_bfloat16 gb_h2  [(size_t)MTOT * CH];
__device__ __nv_bfloat16 gb_hid [(size_t)MTOT * HIDDEN];
__device__ __nv_bfloat16 gb_w[576*192 + 192*192 + 768*192 + 192*768];

__device__ __forceinline__ int gather_row(int m) {
    int win = m >> 6, n = m & 63;
    int b   = win >> 10, rem = win & 1023;
    int wh  = rem >> 5,  ww  = rem & 31;
    int r   = n >> 3,    c   = n & 7;
    int hs  = (wh * 8 + r + 4) & 255;
    int ws_ = (ww * 8 + c + 4) & 255;
    return (b << 16) | (hs << 8) | ws_;
}

__device__ __forceinline__ unsigned smem_u32(const void* p) {
    return (unsigned)__cvta_generic_to_shared(p);
}

// ---------------- fp32 -> bf16 convert ----------------
__global__ void f2bf_kernel(const float* __restrict__ in, __nv_bfloat16* __restrict__ out, int n) {
    int i = blockIdx.x * 256 + threadIdx.x;
    if (i < n) out[i] = __float2bfloat16(in[i]);
}

// ---------------- LayerNorm: one warp per row of 192, bf16 out ----------------
__global__ void ln_kernel(const float* __restrict__ in, const float* __restrict__ g,
                          const float* __restrict__ b, __nv_bfloat16* __restrict__ out, int M) {
    int row  = blockIdx.x * (blockDim.x >> 5) + (threadIdx.x >> 5);
    int lane = threadIdx.x & 31;
    if (row >= M) return;
    const float* rp = in + (size_t)row * CH;
    float v[6];
    float s = 0.f;
#pragma unroll
    for (int i = 0; i < 6; i++) { v[i] = rp[lane + 32 * i]; s += v[i]; }
#pragma unroll
    for (int o = 16; o; o >>= 1) s += __shfl_xor_sync(0xffffffffu, s, o);
    float mean = s * (1.f / 192.f);
    float q = 0.f;
#pragma unroll
    for (int i = 0; i < 6; i++) { float d = v[i] - mean; q += d * d; }
#pragma unroll
    for (int o = 16; o; o >>= 1) q += __shfl_xor_sync(0xffffffffu, q, o);
    float inv = rsqrtf(q * (1.f / 192.f) + 1e-5f);
    __nv_bfloat16* op = out + (size_t)row * CH;
#pragma unroll
    for (int i = 0; i < 6; i++) {
        int col = lane + 32 * i;
        op[col] = __float2bfloat16((v[i] - mean) * inv * g[col] + b[col]);
    }
}

// ---------------- HMMA bf16 GEMM, 128x128 tile, k-step 32, 3-stage cp.async ----------------
// C[m,n] = sum_k A[m,k] * W[n,k]
// EPI: 0 = store bf16; 1 = +bias, exact GELU, bf16; 2 = scatter row, +res[gathered], fp32; 3 = +bias, +res[m], fp32
#define KSTEP 32
#define SPAD 40   // 32 + 8 pad (80B row stride: 16B aligned, ldmatrix conflict-free)

template<int EPI, bool GATHER>
__global__ void __launch_bounds__(256) gemm_mma(
    const __nv_bfloat16* __restrict__ A, const __nv_bfloat16* __restrict__ W,
    const float* __restrict__ bias, const float* __restrict__ res,
    void* __restrict__ Cout, int K, int N)
{
    __shared__ __nv_bfloat16 As[3][128][SPAD];
    __shared__ __nv_bfloat16 Bs[3][128][SPAD];
    const int m0 = blockIdx.x * 128, n0 = blockIdx.y * 128;
    const int t = threadIdx.x, lane = t & 31, wid = t >> 5;
    const int wm = wid & 1, wn = wid >> 1;   // 2 (M) x 4 (N) warps, each 64x32

    // gmem->smem: each thread loads 2x16B for A and 2x16B for B per stage
    const int lr = t >> 2;              // 0..63
    const int lch = (t & 3) * 8;        // k-offset within stage (elements)
    const int ar0 = GATHER ? gather_row(m0 + lr)      : (m0 + lr);
    const int ar1 = GATHER ? gather_row(m0 + 64 + lr) : (m0 + 64 + lr);
    const __nv_bfloat16* Ap0 = A + (size_t)ar0 * K + lch;
    const __nv_bfloat16* Ap1 = A + (size_t)ar1 * K + lch;
    int bg0 = n0 + lr;      if (bg0 >= N) bg0 = 0;
    int bg1 = n0 + 64 + lr; if (bg1 >= N) bg1 = 0;
    const __nv_bfloat16* Wp0 = W + (size_t)bg0 * K + lch;
    const __nv_bfloat16* Wp1 = W + (size_t)bg1 * K + lch;

    float acc[4][4][4];
#pragma unroll
    for (int i = 0; i < 4; i++)
#pragma unroll
        for (int j = 0; j < 4; j++)
#pragma unroll
            for (int q = 0; q < 4; q++) acc[i][j][q] = 0.f;

    const int nk = K / KSTEP;   // >= 6 always

#define LOAD_STAGE(st, ks)                                                              \
    do {                                                                                \
        unsigned _a0 = smem_u32(&As[st][lr][lch]);                                      \
        unsigned _a1 = smem_u32(&As[st][64 + lr][lch]);                                 \
        unsigned _b0 = smem_u32(&Bs[st][lr][lch]);                                      \
        unsigned _b1 = smem_u32(&Bs[st][64 + lr][lch]);                                 \
        const __nv_bfloat16* _pa0 = Ap0 + (ks) * KSTEP;                                 \
        const __nv_bfloat16* _pa1 = Ap1 + (ks) * KSTEP;                                 \
        const __nv_bfloat16* _pb0 = Wp0 + (ks) * KSTEP;                                 \
        const __nv_bfloat16* _pb1 = Wp1 + (ks) * KSTEP;                                 \
        asm volatile("cp.async.cg.shared.global [%0], [%1], 16;\n" :: "r"(_a0), "l"(_pa0)); \
        asm volatile("cp.async.cg.shared.global [%0], [%1], 16;\n" :: "r"(_a1), "l"(_pa1)); \
        asm volatile("cp.async.cg.shared.global [%0], [%1], 16;\n" :: "r"(_b0), "l"(_pb0)); \
        asm volatile("cp.async.cg.shared.global [%0], [%1], 16;\n" :: "r"(_b1), "l"(_pb1)); \
        asm volatile("cp.async.commit_group;\n");                                       \
    } while (0)

    LOAD_STAGE(0, 0);
    LOAD_STAGE(1, 1);

    const int r16 = lane & 15, chh = lane >> 4;

    for (int ks = 0; ks < nk; ks++) {
        if (ks + 1 < nk) asm volatile("cp.async.wait_group 1;\n");
        else             asm volatile("cp.async.wait_group 0;\n");
        __syncthreads();

        if (ks + 2 < nk) {
            int st = ks + 2; st -= (st >= 3) ? 3 : 0; st -= (st >= 3) ? 3 : 0;
            // ks+2 < nk <= 24; compute (ks+2)%3 cheaply
            st = (ks + 2) % 3;
            LOAD_STAGE(st, ks + 2);
        }

        const int buf = ks % 3;
#pragma unroll
        for (int kk = 0; kk < 2; kk++) {
            unsigned a[4][4], b[2][4];
#pragma unroll
            for (int i = 0; i < 4; i++) {
                unsigned addr = smem_u32(&As[buf][wm * 64 + i * 16 + r16][kk * 16 + chh * 8]);
                asm volatile("ldmatrix.sync.aligned.m8n8.x4.shared.b16 {%0,%1,%2,%3}, [%4];"
                    : "=r"(a[i][0]), "=r"(a[i][1]), "=r"(a[i][2]), "=r"(a[i][3]) : "r"(addr));
            }
#pragma unroll
            for (int j2 = 0; j2 < 2; j2++) {
                unsigned addr = smem_u32(&Bs[buf][wn * 32 + j2 * 16 + r16][kk * 16 + chh * 8]);
                asm volatile("ldmatrix.sync.aligned.m8n8.x4.shared.b16 {%0,%1,%2,%3}, [%4];"
                    : "=r"(b[j2][0]), "=r"(b[j2][1]), "=r"(b[j2][2]), "=r"(b[j2][3]) : "r"(addr));
            }
#pragma unroll
            for (int i = 0; i < 4; i++)
#pragma unroll
                for (int j = 0; j < 4; j++) {
                    unsigned b0 = b[j >> 1][j & 1], b1 = b[j >> 1][(j & 1) + 2];
                    asm volatile(
                        "mma.sync.aligned.m16n8k16.row.col.f32.bf16.bf16.f32 "
                        "{%0,%1,%2,%3}, {%4,%5,%6,%7}, {%8,%9}, {%0,%1,%2,%3};"
                        : "+f"(acc[i][j][0]), "+f"(acc[i][j][1]), "+f"(acc[i][j][2]), "+f"(acc[i][j][3])
                        : "r"(a[i][0]), "r"(a[i][1]), "r"(a[i][2]), "r"(a[i][3]), "r"(b0), "r"(b1));
                }
        }
    }
#undef LOAD_STAGE

    // epilogue
#pragma unroll
    for (int i = 0; i < 4; i++) {
        int rbase = m0 + wm * 64 + i * 16 + (lane >> 2);
#pragma unroll
        for (int j = 0; j < 4; j++) {
            int c = n0 + wn * 32 + j * 8 + (lane & 3) * 2;
            if (c < N) {
#pragma unroll
                for (int h = 0; h < 2; h++) {
                    int r = rbase + h * 8;
                    float v0 = acc[i][j][h * 2 + 0];
                    float v1 = acc[i][j][h * 2 + 1];
                    if (bias) { v0 += __ldg(&bias[c]); v1 += __ldg(&bias[c + 1]); }
                    if (EPI == 1) {
                        v0 = 0.5f * v0 * (1.f + erff(v0 * 0.70710678118654752f));
                        v1 = 0.5f * v1 * (1.f + erff(v1 * 0.70710678118654752f));
                    }
                    if (EPI >= 2) {
                        int orow = (EPI == 2) ? gather_row(r) : r;
                        size_t off = (size_t)orow * N + c;
                        float2 rv = *(const float2*)(res + off);
                        float2 ov; ov.x = v0 + rv.x; ov.y = v1 + rv.y;
                        *(float2*)((float*)Cout + off) = ov;
                    } else {
                        __nv_bfloat162 p;
                        p.x = __float2bfloat16(v0); p.y = __float2bfloat16(v1);
                        *(__nv_bfloat162*)((__nv_bfloat16*)Cout + (size_t)r * N + c) = p;
                    }
                }
            }
        }
    }
}

// ---------------- windowed attention: one block per (window, head), 64 threads ----------------
__device__ __forceinline__ int region(int p) { return p < 248 ? 0 : (p < 252 ? 1 : 2); }

__global__ void __launch_bounds__(64) attn_kernel(const __nv_bfloat16* __restrict__ qkv,
                                                  const float* __restrict__ rpb,
                                                  __nv_bfloat16* __restrict__ out) {
    __shared__ float sk[64][32];
    __shared__ float sv[64][32];
    __shared__ float sp[64][65];
    __shared__ float srpb[225];

    const int win = blockIdx.x;
    const int h   = blockIdx.y;
    const int n   = threadIdx.x;

    for (int i = n; i < 225; i += 64) srpb[i] = rpb[i * HEADS + h];

    const size_t base = (size_t)(win * 64 + n) * (3 * CH) + h * HD;
    const float scale = 0.17677669529663687f;

    float q[32];
    {
        const __nv_bfloat162* qp = (const __nv_bfloat162*)(qkv + base);
        const __nv_bfloat162* kp = (const __nv_bfloat162*)(qkv + base + CH);
        const __nv_bfloat162* vp = (const __nv_bfloat162*)(qkv + base + 2 * CH);
#pragma unroll
        for (int i = 0; i < 16; i++) {
            float2 fq = __bfloat1622float2(qp[i]);
            float2 fk = __bfloat1622float2(kp[i]);
            float2 fv = __bfloat1622float2(vp[i]);
            q[2 * i] = fq.x * scale; q[2 * i + 1] = fq.y * scale;
            sk[n][2 * i] = fk.x; sk[n][2 * i + 1] = fk.y;
            sv[n][2 * i] = fv.x; sv[n][2 * i + 1] = fv.y;
        }
    }
    __syncthreads();

    const int rem = win & 1023;
    const int wh = rem >> 5, ww = rem & 31;
    const int ri = n >> 3, ci = n & 7;
    const int idi = region(wh * 8 + ri) * 3 + region(ww * 8 + ci);

    float mx = -1e30f;
    for (int j = 0; j < 64; j++) {
        float a = 0.f;
#pragma unroll
        for (int d4 = 0; d4 < 8; d4++) {
            float4 kv = *(const float4*)&sk[j][d4 * 4];
            a = fmaf(q[d4 * 4 + 0], kv.x, a);
            a = fmaf(q[d4 * 4 + 1], kv.y, a);
            a = fmaf(q[d4 * 4 + 2], kv.z, a);
            a = fmaf(q[d4 * 4 + 3], kv.w, a);
        }
        int rj = j >> 3, cj = j & 7;
        a += srpb[(ri - rj + 7) * 15 + (ci - cj + 7)];
        int idj = region(wh * 8 + rj) * 3 + region(ww * 8 + cj);
        if (idi != idj) a -= 100.f;
        sp[n][j] = a;
        mx = fmaxf(mx, a);
    }

    float sum = 0.f;
    for (int j = 0; j < 64; j++) {
        float e = __expf(sp[n][j] - mx);
        sp[n][j] = e;
        sum += e;
    }
    float inv = 1.f / sum;

    float o[32];
#pragma unroll
    for (int d = 0; d < 32; d++) o[d] = 0.f;
    for (int j = 0; j < 64; j++) {
        float p = sp[n][j];
#pragma unroll
        for (int d4 = 0; d4 < 8; d4++) {
            float4 vv = *(const float4*)&sv[j][d4 * 4];
            o[d4 * 4 + 0] = fmaf(p, vv.x, o[d4 * 4 + 0]);
            o[d4 * 4 + 1] = fmaf(p, vv.y, o[d4 * 4 + 1]);
            o[d4 * 4 + 2] = fmaf(p, vv.z, o[d4 * 4 + 2]);
            o[d4 * 4 + 3] = fmaf(p, vv.w, o[d4 * 4 + 3]);
        }
    }

    __nv_bfloat16* op = out + (size_t)(win * 64 + n) * CH + h * HD;
#pragma unroll
    for (int d2 = 0; d2 < 16; d2++) {
        __nv_bfloat162 p;
        p.x = __float2bfloat16(o[2 * d2] * inv);
        p.y = __float2bfloat16(o[2 * d2 + 1] * inv);
        *(__nv_bfloat162*)&op[2 * d2] = p;
    }
}

// ---------------- launcher ----------------
extern "C" void kernel_launch(void* const* d_in, const int* in_sizes, int n_in,
                              void* d_out, int out_size) {
    const float* x       = (const float*)d_in[0];
    const float* norm1_g = (const float*)d_in[1];
    const float* norm1_b = (const float*)d_in[2];
    const float* qkv_w   = (const float*)d_in[3];
    const float* rpb     = (const float*)d_in[4];
    const float* proj_w  = (const float*)d_in[5];
    const float* proj_b  = (const float*)d_in[6];
    const float* norm2_g = (const float*)d_in[7];
    const float* norm2_b = (const float*)d_in[8];
    const float* mlp_w1  = (const float*)d_in[9];
    const float* mlp_b1  = (const float*)d_in[10];
    const float* mlp_w2  = (const float*)d_in[11];
    const float* mlp_b2  = (const float*)d_in[12];
    float* out = (float*)d_out;

    __nv_bfloat16 *xn, *qkvb, *attnb, *h2, *hid, *wbuf;
    float* x1;
    cudaGetSymbolAddress((void**)&xn,    gb_xn);
    cudaGetSymbolAddress((void**)&qkvb,  gb_qkv);
    cudaGetSymbolAddress((void**)&attnb, gb_attn);
    cudaGetSymbolAddress((void**)&x1,    g_x1);
    cudaGetSymbolAddress((void**)&h2,    gb_h2);
    cudaGetSymbolAddress((void**)&hid,   gb_hid);
    cudaGetSymbolAddress((void**)&wbuf,  gb_w);

    __nv_bfloat16* wq  = wbuf;
    __nv_bfloat16* wp  = wbuf + 576 * 192;
    __nv_bfloat16* w1  = wp   + 192 * 192;
    __nv_bfloat16* w2  = w1   + 768 * 192;

    const int M = MTOT;
    const int LN_BLOCKS = M / 8;

    f2bf_kernel<<<(576 * 192 + 255) / 256, 256>>>(qkv_w,  wq, 576 * 192);
    f2bf_kernel<<<(192 * 192 + 255) / 256, 256>>>(proj_w, wp, 192 * 192);
    f2bf_kernel<<<(768 * 192 + 255) / 256, 256>>>(mlp_w1, w1, 768 * 192);
    f2bf_kernel<<<(192 * 768 + 255) / 256, 256>>>(mlp_w2, w2, 192 * 768);

    ln_kernel<<<LN_BLOCKS, 256>>>(x, norm1_g, norm1_b, xn, M);

    gemm_mma<0, true><<<dim3(M / 128, 5), 256>>>(xn, wq, nullptr, nullptr, qkvb, CH, 3 * CH);

    attn_kernel<<<dim3(2048, HEADS), 64>>>(qkvb, rpb, attnb);

    gemm_mma<2, false><<<dim3(M / 128, 2), 256>>>(attnb, wp, proj_b, x, x1, CH, CH);

    ln_kernel<<<LN_BLOCKS, 256>>>(x1, norm2_g, norm2_b, h2, M);

    gemm_mma<1, false><<<dim3(M / 128, 6), 256>>>(h2, w1, mlp_b1, nullptr, hid, CH, HIDDEN);

    gemm_mma<3, false><<<dim3(M / 128, 2), 256>>>(hid, w2, mlp_b2, x1, out, HIDDEN, CH);
}